// round 1
// baseline (speedup 1.0000x reference)
#include <cuda_runtime.h>
#include <cuda_bf16.h>
#include <math.h>

// Problem constants
#define BATCH 32
#define DIM   384
#define NTOK  1024   // H*W = 32*32

// Tiling
#define TM 64
#define TN 64
#define TK 16

// Scratch (allocation-free rule: __device__ globals)
__device__ float g_q[(size_t)BATCH * DIM * NTOK];
__device__ float g_k[(size_t)BATCH * DIM * NTOK];
__device__ float g_v[(size_t)BATCH * DIM * NTOK];
__device__ float g_s[(size_t)BATCH * NTOK * NTOK];
__device__ float g_o[(size_t)BATCH * DIM * NTOK];

// ---------------------------------------------------------------------------
// NN GEMM + bias: C[b,m,n] = sum_k A[m,k] * B[b,k,n] + bias[m]
// A: (M,K) row-major, shared across batch (weights). B batched (K,N). C batched.
// All dims multiples of tile sizes (M=384, K=384, N=1024).
// ---------------------------------------------------------------------------
__global__ __launch_bounds__(256) void gemm_nn_bias_kernel(
    const float* __restrict__ A, const float* __restrict__ B,
    const float* __restrict__ bias, float* __restrict__ C,
    int M, int K, int N)
{
    const int bz = blockIdx.z;
    const float* Bb = B + (size_t)bz * K * N;
    float* Cb = C + (size_t)bz * M * N;
    const int m0 = blockIdx.y * TM;
    const int n0 = blockIdx.x * TN;

    __shared__ float As[TK][TM + 4];  // As[k][m], padded (transpose-store)
    __shared__ float Bs[TK][TN];      // Bs[k][n]

    const int tid = threadIdx.x;
    const int tx = tid & 15;          // n-dir microtile
    const int ty = tid >> 4;          // m-dir microtile

    // A-tile load mapping: 64 rows x 16 k, float4 along k
    const int ar  = tid >> 2;
    const int ac4 = (tid & 3) * 4;
    // B-tile load mapping: 16 rows x 64 n, float4 along n
    const int br  = tid >> 4;
    const int bc4 = (tid & 15) * 4;

    float acc[4][4] = {};

    for (int k0 = 0; k0 < K; k0 += TK) {
        float4 av = *reinterpret_cast<const float4*>(&A[(size_t)(m0 + ar) * K + k0 + ac4]);
        float4 bv = *reinterpret_cast<const float4*>(&Bb[(size_t)(k0 + br) * N + n0 + bc4]);
        As[ac4 + 0][ar] = av.x;
        As[ac4 + 1][ar] = av.y;
        As[ac4 + 2][ar] = av.z;
        As[ac4 + 3][ar] = av.w;
        *reinterpret_cast<float4*>(&Bs[br][bc4]) = bv;
        __syncthreads();
#pragma unroll
        for (int k = 0; k < TK; k++) {
            float a[4], b[4];
#pragma unroll
            for (int i = 0; i < 4; i++) a[i] = As[k][ty * 4 + i];
#pragma unroll
            for (int j = 0; j < 4; j++) b[j] = Bs[k][tx * 4 + j];
#pragma unroll
            for (int i = 0; i < 4; i++)
#pragma unroll
                for (int j = 0; j < 4; j++)
                    acc[i][j] += a[i] * b[j];
        }
        __syncthreads();
    }

#pragma unroll
    for (int i = 0; i < 4; i++) {
        float bb = bias[m0 + ty * 4 + i];
        float4 r = make_float4(acc[i][0] + bb, acc[i][1] + bb,
                               acc[i][2] + bb, acc[i][3] + bb);
        *reinterpret_cast<float4*>(&Cb[(size_t)(m0 + ty * 4 + i) * N + n0 + tx * 4]) = r;
    }
}

// ---------------------------------------------------------------------------
// TN GEMM (scores): C[b,i,j] = scale * sum_k A[b,k,i] * B[b,k,j]
// A = q (K=DIM rows, M=NTOK cols), B = k. Both loads naturally coalesced.
// ---------------------------------------------------------------------------
__global__ __launch_bounds__(256) void gemm_tn_scale_kernel(
    const float* __restrict__ A, const float* __restrict__ B,
    float* __restrict__ C, int K, int M, int N, float scale)
{
    const int bz = blockIdx.z;
    const float* Ab = A + (size_t)bz * K * M;
    const float* Bb = B + (size_t)bz * K * N;
    float* Cb = C + (size_t)bz * M * N;
    const int m0 = blockIdx.y * TM;
    const int n0 = blockIdx.x * TN;

    __shared__ float As[TK][TM];
    __shared__ float Bs[TK][TN];

    const int tid = threadIdx.x;
    const int tx = tid & 15;
    const int ty = tid >> 4;
    const int lr  = tid >> 4;          // 0..15 (k row)
    const int lc4 = (tid & 15) * 4;    // 0..60 (m/n col, float4)

    float acc[4][4] = {};

    for (int k0 = 0; k0 < K; k0 += TK) {
        float4 av = *reinterpret_cast<const float4*>(&Ab[(size_t)(k0 + lr) * M + m0 + lc4]);
        float4 bv = *reinterpret_cast<const float4*>(&Bb[(size_t)(k0 + lr) * N + n0 + lc4]);
        *reinterpret_cast<float4*>(&As[lr][lc4]) = av;
        *reinterpret_cast<float4*>(&Bs[lr][lc4]) = bv;
        __syncthreads();
#pragma unroll
        for (int k = 0; k < TK; k++) {
            float a[4], b[4];
#pragma unroll
            for (int i = 0; i < 4; i++) a[i] = As[k][ty * 4 + i];
#pragma unroll
            for (int j = 0; j < 4; j++) b[j] = Bs[k][tx * 4 + j];
#pragma unroll
            for (int i = 0; i < 4; i++)
#pragma unroll
                for (int j = 0; j < 4; j++)
                    acc[i][j] += a[i] * b[j];
        }
        __syncthreads();
    }

#pragma unroll
    for (int i = 0; i < 4; i++) {
        float4 r = make_float4(acc[i][0] * scale, acc[i][1] * scale,
                               acc[i][2] * scale, acc[i][3] * scale);
        *reinterpret_cast<float4*>(&Cb[(size_t)(m0 + ty * 4 + i) * N + n0 + tx * 4]) = r;
    }
}

// ---------------------------------------------------------------------------
// Row softmax over last dim (in-place). One CTA per row, ncols = 1024.
// ---------------------------------------------------------------------------
__global__ __launch_bounds__(256) void softmax_rows_kernel(float* __restrict__ S, int ncols)
{
    float* row = S + (size_t)blockIdx.x * ncols;
    const int tid = threadIdx.x;
    __shared__ float red[8];

    float4 v = reinterpret_cast<float4*>(row)[tid];
    float m = fmaxf(fmaxf(v.x, v.y), fmaxf(v.z, v.w));
#pragma unroll
    for (int o = 16; o > 0; o >>= 1)
        m = fmaxf(m, __shfl_xor_sync(0xffffffffu, m, o));
    if ((tid & 31) == 0) red[tid >> 5] = m;
    __syncthreads();
    float mall = fmaxf(fmaxf(red[0], red[1]), fmaxf(red[2], red[3]));
    mall = fmaxf(mall, fmaxf(fmaxf(red[4], red[5]), fmaxf(red[6], red[7])));

    float4 e;
    e.x = expf(v.x - mall);
    e.y = expf(v.y - mall);
    e.z = expf(v.z - mall);
    e.w = expf(v.w - mall);
    float s = e.x + e.y + e.z + e.w;
#pragma unroll
    for (int o = 16; o > 0; o >>= 1)
        s += __shfl_xor_sync(0xffffffffu, s, o);
    __syncthreads();
    if ((tid & 31) == 0) red[tid >> 5] = s;
    __syncthreads();
    float sall = red[0] + red[1] + red[2] + red[3] + red[4] + red[5] + red[6] + red[7];
    float inv = 1.0f / sall;
    e.x *= inv; e.y *= inv; e.z *= inv; e.w *= inv;
    reinterpret_cast<float4*>(row)[tid] = e;
}

// ---------------------------------------------------------------------------
// NT GEMM (attn * V^T): C[b,c,n] = sum_m A[b,c,m] * B[b,n,m]
// A = v (Crows x Mdim), B = attn (N x Mdim). Both m-contiguous -> transpose-store.
// ---------------------------------------------------------------------------
__global__ __launch_bounds__(256) void gemm_nt_kernel(
    const float* __restrict__ A, const float* __restrict__ B,
    float* __restrict__ C, int Crows, int Mdim, int N)
{
    const int bz = blockIdx.z;
    const float* Ab = A + (size_t)bz * Crows * Mdim;
    const float* Bb = B + (size_t)bz * N * Mdim;
    float* Cb = C + (size_t)bz * Crows * N;
    const int c0 = blockIdx.y * TM;
    const int n0 = blockIdx.x * TN;

    __shared__ float As[TK][TM + 4];  // As[m][c]
    __shared__ float Bs[TK][TN + 4];  // Bs[m][n]

    const int tid = threadIdx.x;
    const int tx = tid & 15;
    const int ty = tid >> 4;
    const int lr  = tid >> 2;          // 0..63 (c or n row)
    const int lc4 = (tid & 3) * 4;     // 0..12 (m col, float4)

    float acc[4][4] = {};

    for (int m0 = 0; m0 < Mdim; m0 += TK) {
        float4 av = *reinterpret_cast<const float4*>(&Ab[(size_t)(c0 + lr) * Mdim + m0 + lc4]);
        float4 bv = *reinterpret_cast<const float4*>(&Bb[(size_t)(n0 + lr) * Mdim + m0 + lc4]);
        As[lc4 + 0][lr] = av.x;
        As[lc4 + 1][lr] = av.y;
        As[lc4 + 2][lr] = av.z;
        As[lc4 + 3][lr] = av.w;
        Bs[lc4 + 0][lr] = bv.x;
        Bs[lc4 + 1][lr] = bv.y;
        Bs[lc4 + 2][lr] = bv.z;
        Bs[lc4 + 3][lr] = bv.w;
        __syncthreads();
#pragma unroll
        for (int k = 0; k < TK; k++) {
            float a[4], b[4];
#pragma unroll
            for (int i = 0; i < 4; i++) a[i] = As[k][ty * 4 + i];
#pragma unroll
            for (int j = 0; j < 4; j++) b[j] = Bs[k][tx * 4 + j];
#pragma unroll
            for (int i = 0; i < 4; i++)
#pragma unroll
                for (int j = 0; j < 4; j++)
                    acc[i][j] += a[i] * b[j];
        }
        __syncthreads();
    }

#pragma unroll
    for (int i = 0; i < 4; i++) {
        float4 r = make_float4(acc[i][0], acc[i][1], acc[i][2], acc[i][3]);
        *reinterpret_cast<float4*>(&Cb[(size_t)(c0 + ty * 4 + i) * N + n0 + tx * 4]) = r;
    }
}

// ---------------------------------------------------------------------------
extern "C" void kernel_launch(void* const* d_in, const int* in_sizes, int n_in,
                              void* d_out, int out_size)
{
    const float* rgb = (const float*)d_in[0];
    const float* ms  = (const float*)d_in[1];
    const float* Wq  = (const float*)d_in[2];
    const float* bq  = (const float*)d_in[3];
    const float* Wk  = (const float*)d_in[4];
    const float* bk  = (const float*)d_in[5];
    const float* Wv  = (const float*)d_in[6];
    const float* bv  = (const float*)d_in[7];
    const float* Wf  = (const float*)d_in[8];
    const float* bf  = (const float*)d_in[9];
    float* out = (float*)d_out;

    float *q, *k, *v, *s, *o;
    cudaGetSymbolAddress((void**)&q, g_q);
    cudaGetSymbolAddress((void**)&k, g_k);
    cudaGetSymbolAddress((void**)&v, g_v);
    cudaGetSymbolAddress((void**)&s, g_s);
    cudaGetSymbolAddress((void**)&o, g_o);

    const float scale = 1.0f / sqrtf((float)DIM);

    dim3 blk(256);
    dim3 gProj(NTOK / TN, DIM / TM, BATCH);    // (16, 6, 32)
    dim3 gScore(NTOK / TN, NTOK / TM, BATCH);  // (16, 16, 32)

    gemm_nn_bias_kernel<<<gProj, blk>>>(Wq, rgb, bq, q, DIM, DIM, NTOK);
    gemm_nn_bias_kernel<<<gProj, blk>>>(Wk, ms,  bk, k, DIM, DIM, NTOK);
    gemm_nn_bias_kernel<<<gProj, blk>>>(Wv, ms,  bv, v, DIM, DIM, NTOK);

    gemm_tn_scale_kernel<<<gScore, blk>>>(q, k, s, DIM, NTOK, NTOK, scale);

    softmax_rows_kernel<<<BATCH * NTOK, 256>>>(s, NTOK);

    gemm_nt_kernel<<<gProj, blk>>>(v, s, o, DIM, NTOK, NTOK);

    gemm_nn_bias_kernel<<<gProj, blk>>>(Wf, o, bf, out, DIM, DIM, NTOK);
}

// round 2
// speedup vs baseline: 1.0562x; 1.0562x over previous
#include <cuda_runtime.h>
#include <cuda_bf16.h>
#include <math.h>
#include <stdint.h>

// Problem constants
#define BATCH 32
#define DIM   384
#define NTOK  1024   // H*W

// CTA tile
#define TM 128
#define TN 128
#define TK 16

// smem strides (floats), chosen for conflict-free fragment LDS
#define SA 20    // [m][k] tiles: 16 k + 4 pad
#define SB 136   // [k][n] tiles: 128 + 8 pad

// Scratch (allocation-free rule: __device__ globals)
__device__ float g_q[(size_t)BATCH * DIM * NTOK];
__device__ float g_k[(size_t)BATCH * DIM * NTOK];
__device__ float g_v[(size_t)BATCH * DIM * NTOK];
__device__ float g_s[(size_t)BATCH * NTOK * NTOK];
__device__ float g_o[(size_t)BATCH * DIM * NTOK];

// ---------------------------------------------------------------------------
// tf32 split: x = hi + lo, both tf32-representable (round-to-nearest!)
// ---------------------------------------------------------------------------
__device__ __forceinline__ void split_tf32(float x, float& h, float& l) {
    uint32_t hb;
    asm("cvt.rna.tf32.f32 %0, %1;" : "=r"(hb) : "f"(x));
    h = __uint_as_float(hb);
    float r = x - h;
    uint32_t lb;
    asm("cvt.rna.tf32.f32 %0, %1;" : "=r"(lb) : "f"(r));
    l = __uint_as_float(lb);
}

struct FragA { uint32_t h[4]; uint32_t l[4]; };
struct FragB { uint32_t h[2]; uint32_t l[2]; };

__device__ __forceinline__ void mma1(float acc[4], const uint32_t a[4], const uint32_t b[2]) {
    asm("mma.sync.aligned.m16n8k8.row.col.f32.tf32.tf32.f32 "
        "{%0,%1,%2,%3}, {%4,%5,%6,%7}, {%8,%9}, {%0,%1,%2,%3};"
        : "+f"(acc[0]), "+f"(acc[1]), "+f"(acc[2]), "+f"(acc[3])
        : "r"(a[0]), "r"(a[1]), "r"(a[2]), "r"(a[3]), "r"(b[0]), "r"(b[1]));
}

__device__ __forceinline__ void mma3(float acc[4], const FragA& A, const FragB& B) {
    mma1(acc, A.h, B.l);   // hi * lo
    mma1(acc, A.l, B.h);   // lo * hi
    mma1(acc, A.h, B.h);   // hi * hi
}

// ---------------------------------------------------------------------------
// Staging loaders (256 threads). Source row-major with leading dim ld.
// stage_mk: 128 rows x 16 cols tile -> dst[row*SA + col] (hi/lo split)
// stage_kn: 16 rows x 128 cols tile -> dst[row*SB + col]
// ---------------------------------------------------------------------------
__device__ __forceinline__ void stage_mk(float* __restrict__ Dh, float* __restrict__ Dl,
                                         const float* __restrict__ src, int ld, int tid) {
#pragma unroll
    for (int p = 0; p < 2; p++) {
        int r = (tid >> 2) + p * 64;
        int c4 = (tid & 3) * 4;
        float4 v = *reinterpret_cast<const float4*>(src + (size_t)r * ld + c4);
        float4 h4, l4;
        split_tf32(v.x, h4.x, l4.x);
        split_tf32(v.y, h4.y, l4.y);
        split_tf32(v.z, h4.z, l4.z);
        split_tf32(v.w, h4.w, l4.w);
        *reinterpret_cast<float4*>(&Dh[r * SA + c4]) = h4;
        *reinterpret_cast<float4*>(&Dl[r * SA + c4]) = l4;
    }
}

__device__ __forceinline__ void stage_kn(float* __restrict__ Dh, float* __restrict__ Dl,
                                         const float* __restrict__ src, int ld, int tid) {
#pragma unroll
    for (int p = 0; p < 2; p++) {
        int r = p * 8 + (tid >> 5);
        int c4 = (tid & 31) * 4;
        float4 v = *reinterpret_cast<const float4*>(src + (size_t)r * ld + c4);
        float4 h4, l4;
        split_tf32(v.x, h4.x, l4.x);
        split_tf32(v.y, h4.y, l4.y);
        split_tf32(v.z, h4.z, l4.z);
        split_tf32(v.w, h4.w, l4.w);
        *reinterpret_cast<float4*>(&Dh[r * SB + c4]) = h4;
        *reinterpret_cast<float4*>(&Dl[r * SB + c4]) = l4;
    }
}

// ---------------------------------------------------------------------------
// Fragment loaders. g = lane>>2, q = lane&3.
// ---------------------------------------------------------------------------
__device__ __forceinline__ FragA ldA_mk(const float* Ah, const float* Al,
                                        int rb, int kc, int g, int q) {
    FragA f;
    int i00 = (rb + g) * SA + kc + q;
    int i10 = (rb + g + 8) * SA + kc + q;
    f.h[0] = __float_as_uint(Ah[i00]);
    f.h[1] = __float_as_uint(Ah[i10]);
    f.h[2] = __float_as_uint(Ah[i00 + 4]);
    f.h[3] = __float_as_uint(Ah[i10 + 4]);
    f.l[0] = __float_as_uint(Al[i00]);
    f.l[1] = __float_as_uint(Al[i10]);
    f.l[2] = __float_as_uint(Al[i00 + 4]);
    f.l[3] = __float_as_uint(Al[i10 + 4]);
    return f;
}

__device__ __forceinline__ FragA ldA_km(const float* Ah, const float* Al,
                                        int rb, int kc, int g, int q) {
    FragA f;
    int i0 = (kc + q) * SB + rb + g;
    int i2 = (kc + q + 4) * SB + rb + g;
    f.h[0] = __float_as_uint(Ah[i0]);
    f.h[1] = __float_as_uint(Ah[i0 + 8]);
    f.h[2] = __float_as_uint(Ah[i2]);
    f.h[3] = __float_as_uint(Ah[i2 + 8]);
    f.l[0] = __float_as_uint(Al[i0]);
    f.l[1] = __float_as_uint(Al[i0 + 8]);
    f.l[2] = __float_as_uint(Al[i2]);
    f.l[3] = __float_as_uint(Al[i2 + 8]);
    return f;
}

__device__ __forceinline__ FragB ldB_kn(const float* Bh, const float* Bl,
                                        int cb, int kc, int g, int q) {
    FragB f;
    int i0 = (kc + q) * SB + cb + g;
    int i1 = (kc + q + 4) * SB + cb + g;
    f.h[0] = __float_as_uint(Bh[i0]);
    f.h[1] = __float_as_uint(Bh[i1]);
    f.l[0] = __float_as_uint(Bl[i0]);
    f.l[1] = __float_as_uint(Bl[i1]);
    return f;
}

__device__ __forceinline__ FragB ldB_nk(const float* Bh, const float* Bl,
                                        int cb, int kc, int g, int q) {
    FragB f;
    int i0 = (cb + g) * SA + kc + q;
    f.h[0] = __float_as_uint(Bh[i0]);
    f.h[1] = __float_as_uint(Bh[i0 + 4]);
    f.l[0] = __float_as_uint(Bl[i0]);
    f.l[1] = __float_as_uint(Bl[i0 + 4]);
    return f;
}

#define COMPUTE_CHUNK(LD_A, LD_B)                                          \
    {                                                                      \
        FragA fa[4];                                                       \
        FragB fb[4];                                                       \
        _Pragma("unroll")                                                  \
        for (int mt = 0; mt < 4; mt++)                                     \
            fa[mt] = LD_A(Ah, Al, wm * 64 + mt * 16, kc, g, q);            \
        _Pragma("unroll")                                                  \
        for (int nt = 0; nt < 4; nt++)                                     \
            fb[nt] = LD_B(Bh, Bl, wn * 32 + nt * 8, kc, g, q);             \
        _Pragma("unroll")                                                  \
        for (int mt = 0; mt < 4; mt++)                                     \
            _Pragma("unroll")                                              \
            for (int nt = 0; nt < 4; nt++)                                 \
                mma3(acc[mt][nt], fa[mt], fb[nt]);                         \
    }

// ---------------------------------------------------------------------------
// Projection GEMM (+bias): C[b](M x N) = W(M x K) x X[b](K x N) + bias
// W row-major k-contig, X row-major n-contig.
// ---------------------------------------------------------------------------
__global__ __launch_bounds__(256) void k_proj(
    const float* __restrict__ W, const float* __restrict__ X,
    const float* __restrict__ bias, float* __restrict__ C, int K, int N)
{
    __shared__ float Ah[128 * SA], Al[128 * SA];
    __shared__ float Bh[16 * SB], Bl[16 * SB];

    const int tid = threadIdx.x;
    const int wid = tid >> 5, lane = tid & 31;
    const int wm = wid >> 2, wn = wid & 3;
    const int g = lane >> 2, q = lane & 3;
    const int m0 = blockIdx.y * TM, n0 = blockIdx.x * TN;
    const float* Xb = X + (size_t)blockIdx.z * K * N;
    float* Cb = C + (size_t)blockIdx.z * gridDim.y * TM * N;

    float acc[4][4][4] = {};

    for (int k0 = 0; k0 < K; k0 += TK) {
        stage_mk(Ah, Al, W + (size_t)m0 * K + k0, K, tid);
        stage_kn(Bh, Bl, Xb + (size_t)k0 * N + n0, N, tid);
        __syncthreads();
#pragma unroll
        for (int kc = 0; kc < TK; kc += 8)
            COMPUTE_CHUNK(ldA_mk, ldB_kn)
        __syncthreads();
    }

#pragma unroll
    for (int mt = 0; mt < 4; mt++) {
        int r0 = m0 + wm * 64 + mt * 16 + g;
        float b0 = bias[r0], b1 = bias[r0 + 8];
#pragma unroll
        for (int nt = 0; nt < 4; nt++) {
            int c = n0 + wn * 32 + nt * 8 + 2 * q;
            *reinterpret_cast<float2*>(&Cb[(size_t)r0 * N + c]) =
                make_float2(acc[mt][nt][0] + b0, acc[mt][nt][1] + b0);
            *reinterpret_cast<float2*>(&Cb[(size_t)(r0 + 8) * N + c]) =
                make_float2(acc[mt][nt][2] + b1, acc[mt][nt][3] + b1);
        }
    }
}

// ---------------------------------------------------------------------------
// Scores GEMM: C[b](M x N) = scale * A[b]^T x B[b]; A,B stored (K x M/N) n-contig
// ---------------------------------------------------------------------------
__global__ __launch_bounds__(256) void k_scores(
    const float* __restrict__ Aq, const float* __restrict__ Bk,
    float* __restrict__ C, int K, int M, int N, float scale)
{
    __shared__ float Ah[16 * SB], Al[16 * SB];
    __shared__ float Bh[16 * SB], Bl[16 * SB];

    const int tid = threadIdx.x;
    const int wid = tid >> 5, lane = tid & 31;
    const int wm = wid >> 2, wn = wid & 3;
    const int g = lane >> 2, q = lane & 3;
    const int m0 = blockIdx.y * TM, n0 = blockIdx.x * TN;
    const float* Ab = Aq + (size_t)blockIdx.z * K * M;
    const float* Bb = Bk + (size_t)blockIdx.z * K * N;
    float* Cb = C + (size_t)blockIdx.z * M * N;

    float acc[4][4][4] = {};

    for (int k0 = 0; k0 < K; k0 += TK) {
        stage_kn(Ah, Al, Ab + (size_t)k0 * M + m0, M, tid);
        stage_kn(Bh, Bl, Bb + (size_t)k0 * N + n0, N, tid);
        __syncthreads();
#pragma unroll
        for (int kc = 0; kc < TK; kc += 8)
            COMPUTE_CHUNK(ldA_km, ldB_kn)
        __syncthreads();
    }

#pragma unroll
    for (int mt = 0; mt < 4; mt++) {
        int r0 = m0 + wm * 64 + mt * 16 + g;
#pragma unroll
        for (int nt = 0; nt < 4; nt++) {
            int c = n0 + wn * 32 + nt * 8 + 2 * q;
            *reinterpret_cast<float2*>(&Cb[(size_t)r0 * N + c]) =
                make_float2(acc[mt][nt][0] * scale, acc[mt][nt][1] * scale);
            *reinterpret_cast<float2*>(&Cb[(size_t)(r0 + 8) * N + c]) =
                make_float2(acc[mt][nt][2] * scale, acc[mt][nt][3] * scale);
        }
    }
}

// ---------------------------------------------------------------------------
// AV GEMM: C[b](M x N) = V[b](M x K) x Attn[b](N x K)^T ; both k-contig rows
// ---------------------------------------------------------------------------
__global__ __launch_bounds__(256) void k_av(
    const float* __restrict__ V, const float* __restrict__ At,
    float* __restrict__ C, int K, int N)
{
    __shared__ float Ah[128 * SA], Al[128 * SA];
    __shared__ float Bh[128 * SA], Bl[128 * SA];

    const int tid = threadIdx.x;
    const int wid = tid >> 5, lane = tid & 31;
    const int wm = wid >> 2, wn = wid & 3;
    const int g = lane >> 2, q = lane & 3;
    const int m0 = blockIdx.y * TM, n0 = blockIdx.x * TN;
    const float* Vb = V + (size_t)blockIdx.z * gridDim.y * TM * K;
    const float* Ab = At + (size_t)blockIdx.z * N * K;
    float* Cb = C + (size_t)blockIdx.z * gridDim.y * TM * N;

    float acc[4][4][4] = {};

    for (int k0 = 0; k0 < K; k0 += TK) {
        stage_mk(Ah, Al, Vb + (size_t)m0 * K + k0, K, tid);
        stage_mk(Bh, Bl, Ab + (size_t)n0 * K + k0, K, tid);
        __syncthreads();
#pragma unroll
        for (int kc = 0; kc < TK; kc += 8)
            COMPUTE_CHUNK(ldA_mk, ldB_nk)
        __syncthreads();
    }

#pragma unroll
    for (int mt = 0; mt < 4; mt++) {
        int r0 = m0 + wm * 64 + mt * 16 + g;
#pragma unroll
        for (int nt = 0; nt < 4; nt++) {
            int c = n0 + wn * 32 + nt * 8 + 2 * q;
            *reinterpret_cast<float2*>(&Cb[(size_t)r0 * N + c]) =
                make_float2(acc[mt][nt][0], acc[mt][nt][1]);
            *reinterpret_cast<float2*>(&Cb[(size_t)(r0 + 8) * N + c]) =
                make_float2(acc[mt][nt][2], acc[mt][nt][3]);
        }
    }
}

// ---------------------------------------------------------------------------
// Row softmax over last dim (in-place). One CTA per row, ncols = 1024.
// ---------------------------------------------------------------------------
__global__ __launch_bounds__(256) void softmax_rows_kernel(float* __restrict__ S, int ncols)
{
    float* row = S + (size_t)blockIdx.x * ncols;
    const int tid = threadIdx.x;
    __shared__ float red[8];

    float4 v = reinterpret_cast<float4*>(row)[tid];
    float m = fmaxf(fmaxf(v.x, v.y), fmaxf(v.z, v.w));
#pragma unroll
    for (int o = 16; o > 0; o >>= 1)
        m = fmaxf(m, __shfl_xor_sync(0xffffffffu, m, o));
    if ((tid & 31) == 0) red[tid >> 5] = m;
    __syncthreads();
    float mall = fmaxf(fmaxf(red[0], red[1]), fmaxf(red[2], red[3]));
    mall = fmaxf(mall, fmaxf(fmaxf(red[4], red[5]), fmaxf(red[6], red[7])));

    float4 e;
    e.x = expf(v.x - mall);
    e.y = expf(v.y - mall);
    e.z = expf(v.z - mall);
    e.w = expf(v.w - mall);
    float s = e.x + e.y + e.z + e.w;
#pragma unroll
    for (int o = 16; o > 0; o >>= 1)
        s += __shfl_xor_sync(0xffffffffu, s, o);
    __syncthreads();
    if ((tid & 31) == 0) red[tid >> 5] = s;
    __syncthreads();
    float sall = red[0] + red[1] + red[2] + red[3] + red[4] + red[5] + red[6] + red[7];
    float inv = 1.0f / sall;
    e.x *= inv; e.y *= inv; e.z *= inv; e.w *= inv;
    reinterpret_cast<float4*>(row)[tid] = e;
}

// ---------------------------------------------------------------------------
extern "C" void kernel_launch(void* const* d_in, const int* in_sizes, int n_in,
                              void* d_out, int out_size)
{
    const float* rgb = (const float*)d_in[0];
    const float* ms  = (const float*)d_in[1];
    const float* Wq  = (const float*)d_in[2];
    const float* bq  = (const float*)d_in[3];
    const float* Wk  = (const float*)d_in[4];
    const float* bk  = (const float*)d_in[5];
    const float* Wv  = (const float*)d_in[6];
    const float* bv  = (const float*)d_in[7];
    const float* Wf  = (const float*)d_in[8];
    const float* bf  = (const float*)d_in[9];
    float* out = (float*)d_out;

    float *q, *k, *v, *s, *o;
    cudaGetSymbolAddress((void**)&q, g_q);
    cudaGetSymbolAddress((void**)&k, g_k);
    cudaGetSymbolAddress((void**)&v, g_v);
    cudaGetSymbolAddress((void**)&s, g_s);
    cudaGetSymbolAddress((void**)&o, g_o);

    const float scale = 1.0f / sqrtf((float)DIM);

    dim3 blk(256);
    dim3 gProj(NTOK / TN, DIM / TM, BATCH);    // (8, 3, 32)
    dim3 gScore(NTOK / TN, NTOK / TM, BATCH);  // (8, 8, 32)

    k_proj<<<gProj, blk>>>(Wq, rgb, bq, q, DIM, NTOK);
    k_proj<<<gProj, blk>>>(Wk, ms,  bk, k, DIM, NTOK);
    k_proj<<<gProj, blk>>>(Wv, ms,  bv, v, DIM, NTOK);

    k_scores<<<gScore, blk>>>(q, k, s, DIM, NTOK, NTOK, scale);

    softmax_rows_kernel<<<BATCH * NTOK, 256>>>(s, NTOK);

    k_av<<<gProj, blk>>>(v, s, o, NTOK, NTOK);

    k_proj<<<gProj, blk>>>(Wf, o, bf, out, DIM, NTOK);
}

// round 3
// speedup vs baseline: 1.6405x; 1.5531x over previous
#include <cuda_runtime.h>
#include <cuda_bf16.h>
#include <math.h>
#include <stdint.h>

#define BATCH 32
#define DIM   384
#define NTOK  1024

// Scratch (allocation-free rule: __device__ globals)
__device__ float g_qT[(size_t)BATCH * NTOK * DIM];  // [n][d]
__device__ float g_kT[(size_t)BATCH * NTOK * DIM];  // [n][d]
__device__ float g_v [(size_t)BATCH * DIM * NTOK];  // [d][n]
__device__ float g_s [(size_t)BATCH * NTOK * NTOK]; // [i][j]
__device__ float g_oT[(size_t)BATCH * NTOK * DIM];  // [n][d]
__device__ float g_t1[(size_t)BATCH * NTOK * DIM];  // rgb^T [n][c]
__device__ float g_t2[(size_t)BATCH * NTOK * DIM];  // ms^T  [n][c]

// ---------------------------------------------------------------------------
// bf16 split + pack helpers
// ---------------------------------------------------------------------------
__device__ __forceinline__ uint32_t pk(__nv_bfloat16 x, __nv_bfloat16 y) {
    return (uint32_t)__bfloat16_as_ushort(x) | ((uint32_t)__bfloat16_as_ushort(y) << 16);
}

// Stage 8 consecutive-k floats (two float4) into hi/lo bf16 tiles.
// Row-major smem tile: 128 rows x 8 u32 (16 bf16), col swizzle c' = c ^ (r&4).
__device__ __forceinline__ void stage8(uint32_t* __restrict__ dh, uint32_t* __restrict__ dl,
                                       float4 v0, float4 v1, int r, int h) {
    float f[8] = {v0.x, v0.y, v0.z, v0.w, v1.x, v1.y, v1.z, v1.w};
    uint32_t hp[4], lp[4];
#pragma unroll
    for (int i = 0; i < 4; i++) {
        float x0 = f[2 * i], x1 = f[2 * i + 1];
        __nv_bfloat16 h0 = __float2bfloat16(x0), h1 = __float2bfloat16(x1);
        float r0 = x0 - __bfloat162float(h0);
        float r1 = x1 - __bfloat162float(h1);
        __nv_bfloat16 l0 = __float2bfloat16(r0), l1 = __float2bfloat16(r1);
        hp[i] = pk(h0, h1);
        lp[i] = pk(l0, l1);
    }
    int cb = (4 * h) ^ (r & 4);
    *reinterpret_cast<uint4*>(&dh[r * 8 + cb]) = make_uint4(hp[0], hp[1], hp[2], hp[3]);
    *reinterpret_cast<uint4*>(&dl[r * 8 + cb]) = make_uint4(lp[0], lp[1], lp[2], lp[3]);
}

// ldmatrix x4: A fragment (16x16 bf16) for m16n8k16
__device__ __forceinline__ void ldmA(uint32_t f[4], const uint32_t* base, int rb, int lane) {
    int t = lane >> 3, rr = lane & 7;
    int row = rb + rr + (t & 1) * 8;
    int c = ((t >> 1) << 2) ^ (row & 4);
    uint32_t sa = (uint32_t)__cvta_generic_to_shared(&base[row * 8 + c]);
    asm volatile("ldmatrix.sync.aligned.m8n8.x4.shared.b16 {%0,%1,%2,%3}, [%4];"
                 : "=r"(f[0]), "=r"(f[1]), "=r"(f[2]), "=r"(f[3]) : "r"(sa));
}

// ldmatrix x2: B fragment (8 n-rows x 16 k) for m16n8k16
__device__ __forceinline__ void ldmB(uint32_t f[2], const uint32_t* base, int cb, int lane) {
    int row = cb + (lane & 7);
    int c = (((lane >> 3) & 1) << 2) ^ (row & 4);
    uint32_t sa = (uint32_t)__cvta_generic_to_shared(&base[row * 8 + c]);
    asm volatile("ldmatrix.sync.aligned.m8n8.x2.shared.b16 {%0,%1}, [%2];"
                 : "=r"(f[0]), "=r"(f[1]) : "r"(sa));
}

__device__ __forceinline__ void mma(float acc[4], const uint32_t a[4], const uint32_t b[2]) {
    asm volatile("mma.sync.aligned.m16n8k16.row.col.f32.bf16.bf16.f32 "
                 "{%0,%1,%2,%3}, {%4,%5,%6,%7}, {%8,%9}, {%0,%1,%2,%3};"
                 : "+f"(acc[0]), "+f"(acc[1]), "+f"(acc[2]), "+f"(acc[3])
                 : "r"(a[0]), "r"(a[1]), "r"(a[2]), "r"(a[3]), "r"(b[0]), "r"(b[1]));
}

// ---------------------------------------------------------------------------
// Universal NT GEMM, bf16x3 split, double-buffered.
// C[b][m][n] = scale * sum_k A[b][m][k] * B[b][n][k]  (+ bias per BM)
// BM: 0 none, 1 row-bias bias[m], 2 col-bias bias[n]
// M, N multiples of 128; K multiple of 16.
// ---------------------------------------------------------------------------
template<int BM>
__global__ __launch_bounds__(256) void k_gemm(
    const float* __restrict__ A, const float* __restrict__ B,
    const float* __restrict__ bias, float* __restrict__ C,
    int M, int N, int K, size_t strA, size_t strB, size_t strC, float scale)
{
    __shared__ uint32_t sm[2][4][128 * 8]; // [buf][Ahi,Alo,Bhi,Blo][128x8]

    const int tid = threadIdx.x, lane = tid & 31, wid = tid >> 5;
    const int wm = wid >> 2, wn = wid & 3, g = lane >> 2, q = lane & 3;
    const int m0 = blockIdx.y * 128, n0 = blockIdx.x * 128;
    const float* Ab = A + (size_t)blockIdx.z * strA;
    const float* Bb = B + (size_t)blockIdx.z * strB;
    float* Cb = C + (size_t)blockIdx.z * strC;

    const int r = tid >> 1, h = tid & 1;
    const float* pA = Ab + (size_t)(m0 + r) * K + 8 * h;
    const float* pB = Bb + (size_t)(n0 + r) * K + 8 * h;

    float acc[4][4][4] = {};
    const int nIt = K >> 4;

    float4 ra0 = *reinterpret_cast<const float4*>(pA);
    float4 ra1 = *reinterpret_cast<const float4*>(pA + 4);
    float4 rb0 = *reinterpret_cast<const float4*>(pB);
    float4 rb1 = *reinterpret_cast<const float4*>(pB + 4);
    stage8(sm[0][0], sm[0][1], ra0, ra1, r, h);
    stage8(sm[0][2], sm[0][3], rb0, rb1, r, h);
    __syncthreads();

    for (int it = 0; it < nIt; it++) {
        const int cur = it & 1;
        if (it + 1 < nIt) {
            const float* qA = pA + (it + 1) * 16;
            const float* qB = pB + (it + 1) * 16;
            ra0 = *reinterpret_cast<const float4*>(qA);
            ra1 = *reinterpret_cast<const float4*>(qA + 4);
            rb0 = *reinterpret_cast<const float4*>(qB);
            rb1 = *reinterpret_cast<const float4*>(qB + 4);
        }

        uint32_t ah[4][4], al[4][4], bh[4][2], bl[4][2];
#pragma unroll
        for (int mt = 0; mt < 4; mt++) {
            ldmA(ah[mt], sm[cur][0], wm * 64 + mt * 16, lane);
            ldmA(al[mt], sm[cur][1], wm * 64 + mt * 16, lane);
        }
#pragma unroll
        for (int nt = 0; nt < 4; nt++) {
            ldmB(bh[nt], sm[cur][2], wn * 32 + nt * 8, lane);
            ldmB(bl[nt], sm[cur][3], wn * 32 + nt * 8, lane);
        }
#pragma unroll
        for (int mt = 0; mt < 4; mt++)
#pragma unroll
            for (int nt = 0; nt < 4; nt++) {
                mma(acc[mt][nt], ah[mt], bl[nt]);
                mma(acc[mt][nt], al[mt], bh[nt]);
                mma(acc[mt][nt], ah[mt], bh[nt]);
            }

        if (it + 1 < nIt) {
            const int nb = 1 - cur;
            stage8(sm[nb][0], sm[nb][1], ra0, ra1, r, h);
            stage8(sm[nb][2], sm[nb][3], rb0, rb1, r, h);
            __syncthreads();
        }
    }

#pragma unroll
    for (int mt = 0; mt < 4; mt++) {
        const int rr = m0 + wm * 64 + mt * 16 + g;
        float br0 = 0.f, br1 = 0.f;
        if (BM == 1) { br0 = bias[rr]; br1 = bias[rr + 8]; }
#pragma unroll
        for (int nt = 0; nt < 4; nt++) {
            const int cc = n0 + wn * 32 + nt * 8 + 2 * q;
            float v0 = acc[mt][nt][0] * scale, v1 = acc[mt][nt][1] * scale;
            float v2 = acc[mt][nt][2] * scale, v3 = acc[mt][nt][3] * scale;
            if (BM == 1) { v0 += br0; v1 += br0; v2 += br1; v3 += br1; }
            if (BM == 2) {
                float bc0 = bias[cc], bc1 = bias[cc + 1];
                v0 += bc0; v1 += bc1; v2 += bc0; v3 += bc1;
            }
            *reinterpret_cast<float2*>(&Cb[(size_t)rr * N + cc]) = make_float2(v0, v1);
            *reinterpret_cast<float2*>(&Cb[(size_t)(rr + 8) * N + cc]) = make_float2(v2, v3);
        }
    }
}

// ---------------------------------------------------------------------------
// f32 transpose [DIM][NTOK] -> [NTOK][DIM], batched.
// ---------------------------------------------------------------------------
__global__ __launch_bounds__(256) void k_transpose(const float* __restrict__ in,
                                                   float* __restrict__ out)
{
    __shared__ float t[32][33];
    const float* ib = in + (size_t)blockIdx.z * DIM * NTOK;
    float* ob = out + (size_t)blockIdx.z * NTOK * DIM;
    const int n0 = blockIdx.x * 32, c0 = blockIdx.y * 32;
    const int tx = threadIdx.x & 31, ty = threadIdx.x >> 5;
#pragma unroll
    for (int j = 0; j < 4; j++)
        t[ty + 8 * j][tx] = ib[(size_t)(c0 + ty + 8 * j) * NTOK + n0 + tx];
    __syncthreads();
#pragma unroll
    for (int j = 0; j < 4; j++)
        ob[(size_t)(n0 + ty + 8 * j) * DIM + c0 + tx] = t[tx][ty + 8 * j];
}

// ---------------------------------------------------------------------------
// Row softmax (in-place), ncols = 1024, one CTA/row.
// ---------------------------------------------------------------------------
__global__ __launch_bounds__(256) void softmax_rows_kernel(float* __restrict__ S)
{
    float* row = S + (size_t)blockIdx.x * NTOK;
    const int tid = threadIdx.x;
    __shared__ float red[8];

    float4 v = reinterpret_cast<float4*>(row)[tid];
    float m = fmaxf(fmaxf(v.x, v.y), fmaxf(v.z, v.w));
#pragma unroll
    for (int o = 16; o > 0; o >>= 1)
        m = fmaxf(m, __shfl_xor_sync(0xffffffffu, m, o));
    if ((tid & 31) == 0) red[tid >> 5] = m;
    __syncthreads();
    float mall = fmaxf(fmaxf(red[0], red[1]), fmaxf(red[2], red[3]));
    mall = fmaxf(mall, fmaxf(fmaxf(red[4], red[5]), fmaxf(red[6], red[7])));

    float4 e;
    e.x = expf(v.x - mall);
    e.y = expf(v.y - mall);
    e.z = expf(v.z - mall);
    e.w = expf(v.w - mall);
    float s = e.x + e.y + e.z + e.w;
#pragma unroll
    for (int o = 16; o > 0; o >>= 1)
        s += __shfl_xor_sync(0xffffffffu, s, o);
    __syncthreads();
    if ((tid & 31) == 0) red[tid >> 5] = s;
    __syncthreads();
    float sall = red[0] + red[1] + red[2] + red[3] + red[4] + red[5] + red[6] + red[7];
    float inv = 1.0f / sall;
    e.x *= inv; e.y *= inv; e.z *= inv; e.w *= inv;
    reinterpret_cast<float4*>(row)[tid] = e;
}

// ---------------------------------------------------------------------------
extern "C" void kernel_launch(void* const* d_in, const int* in_sizes, int n_in,
                              void* d_out, int out_size)
{
    const float* rgb = (const float*)d_in[0];
    const float* ms  = (const float*)d_in[1];
    const float* Wq  = (const float*)d_in[2];
    const float* bq  = (const float*)d_in[3];
    const float* Wk  = (const float*)d_in[4];
    const float* bk  = (const float*)d_in[5];
    const float* Wv  = (const float*)d_in[6];
    const float* bv  = (const float*)d_in[7];
    const float* Wf  = (const float*)d_in[8];
    const float* bf  = (const float*)d_in[9];
    float* out = (float*)d_out;

    float *qT, *kT, *v, *s, *oT, *t1, *t2;
    cudaGetSymbolAddress((void**)&qT, g_qT);
    cudaGetSymbolAddress((void**)&kT, g_kT);
    cudaGetSymbolAddress((void**)&v,  g_v);
    cudaGetSymbolAddress((void**)&s,  g_s);
    cudaGetSymbolAddress((void**)&oT, g_oT);
    cudaGetSymbolAddress((void**)&t1, g_t1);
    cudaGetSymbolAddress((void**)&t2, g_t2);

    const float scale = 1.0f / sqrtf((float)DIM);
    const size_t ND = (size_t)NTOK * DIM;   // 393216
    const size_t NN = (size_t)NTOK * NTOK;  // 1048576

    dim3 blk(256);
    dim3 gT(NTOK / 32, DIM / 32, BATCH);

    k_transpose<<<gT, blk>>>(rgb, t1);
    k_transpose<<<gT, blk>>>(ms,  t2);

    // qT[n][d] = rgbT[n][c] * Wq[d][c] + bq[d]  (col bias)
    dim3 gQ(DIM / 128, NTOK / 128, BATCH);
    k_gemm<2><<<gQ, blk>>>(t1, Wq, bq, qT, NTOK, DIM, DIM, ND, 0, ND, 1.0f);
    k_gemm<2><<<gQ, blk>>>(t2, Wk, bk, kT, NTOK, DIM, DIM, ND, 0, ND, 1.0f);

    // v[d][n] = Wv[d][c] * msT[n][c] + bv[d]  (row bias)
    dim3 gV(NTOK / 128, DIM / 128, BATCH);
    k_gemm<1><<<gV, blk>>>(Wv, t2, bv, v, DIM, NTOK, DIM, 0, ND, ND, 1.0f);

    // S[i][j] = scale * qT[i][:] . kT[j][:]
    dim3 gS(NTOK / 128, NTOK / 128, BATCH);
    k_gemm<0><<<gS, blk>>>(qT, kT, nullptr, s, NTOK, NTOK, DIM, ND, ND, NN, scale);

    softmax_rows_kernel<<<BATCH * NTOK, 256>>>(s);

    // oT[n][d] = P[n][m] . v[d][m]
    k_gemm<0><<<gQ, blk>>>(s, v, nullptr, oT, NTOK, DIM, NTOK, NN, ND, ND, 1.0f);

    // out[d][n] = Wf[d][c] . oT[n][c] + bf[d]  (row bias)
    k_gemm<1><<<gV, blk>>>(Wf, oT, bf, out, DIM, NTOK, DIM, 0, ND, ND, 1.0f);
}

// round 4
// speedup vs baseline: 2.1300x; 1.2984x over previous
#include <cuda_runtime.h>
#include <cuda_bf16.h>
#include <math.h>
#include <stdint.h>

#define BATCH 32
#define DIM   384
#define NTOK  1024
#define STAGES 3

typedef __nv_bfloat16 bf16;

// ---------------------------------------------------------------------------
// Scratch (allocation-free rule: __device__ globals). All operands pre-split
// into hi/lo bf16 pairs; S kept in f32 for softmax precision.
// ---------------------------------------------------------------------------
#define ND ((size_t)BATCH * NTOK * DIM)
#define NN ((size_t)BATCH * NTOK * NTOK)
#define WW ((size_t)DIM * DIM)

__device__ bf16 g_t1h[ND], g_t1l[ND];   // rgb^T [n][c]
__device__ bf16 g_t2h[ND], g_t2l[ND];   // ms^T  [n][c]
__device__ bf16 g_qh[ND],  g_ql[ND];    // qT [n][d]
__device__ bf16 g_kh[ND],  g_kl[ND];    // kT [n][d]
__device__ bf16 g_vh[ND],  g_vl[ND];    // v  [d][n]
__device__ bf16 g_oh[ND],  g_ol[ND];    // oT [n][d]
__device__ bf16 g_Ph[NN],  g_Pl[NN];    // attn [i][m]
__device__ float g_s[NN];               // scores f32
__device__ bf16 g_wh[4 * WW], g_wl[4 * WW]; // Wq,Wk,Wv,Wf split

// ---------------------------------------------------------------------------
// helpers
// ---------------------------------------------------------------------------
__device__ __forceinline__ void split1(float x, bf16& h, bf16& l) {
    h = __float2bfloat16(x);
    l = __float2bfloat16(x - __bfloat162float(h));
}

__device__ __forceinline__ void cpasync16(uint32_t dst, const void* src) {
    asm volatile("cp.async.cg.shared.global [%0], [%1], 16;" :: "r"(dst), "l"(src));
}

__device__ __forceinline__ void ldmA(uint32_t f[4], const uint32_t* base, int rb, int lane) {
    int t = lane >> 3, rr = lane & 7;
    int row = rb + rr + (t & 1) * 8;
    int c = ((t >> 1) << 2) ^ (row & 4);
    uint32_t sa = (uint32_t)__cvta_generic_to_shared(&base[row * 8 + c]);
    asm volatile("ldmatrix.sync.aligned.m8n8.x4.shared.b16 {%0,%1,%2,%3}, [%4];"
                 : "=r"(f[0]), "=r"(f[1]), "=r"(f[2]), "=r"(f[3]) : "r"(sa));
}

__device__ __forceinline__ void ldmB(uint32_t f[2], const uint32_t* base, int cb, int lane) {
    int row = cb + (lane & 7);
    int c = (((lane >> 3) & 1) << 2) ^ (row & 4);
    uint32_t sa = (uint32_t)__cvta_generic_to_shared(&base[row * 8 + c]);
    asm volatile("ldmatrix.sync.aligned.m8n8.x2.shared.b16 {%0,%1}, [%2];"
                 : "=r"(f[0]), "=r"(f[1]) : "r"(sa));
}

__device__ __forceinline__ void mma(float acc[4], const uint32_t a[4], const uint32_t b[2]) {
    asm volatile("mma.sync.aligned.m16n8k16.row.col.f32.bf16.bf16.f32 "
                 "{%0,%1,%2,%3}, {%4,%5,%6,%7}, {%8,%9}, {%0,%1,%2,%3};"
                 : "+f"(acc[0]), "+f"(acc[1]), "+f"(acc[2]), "+f"(acc[3])
                 : "r"(a[0]), "r"(a[1]), "r"(a[2]), "r"(a[3]), "r"(b[0]), "r"(b[1]));
}

// ---------------------------------------------------------------------------
// Universal NT GEMM over pre-split bf16 operands, cp.async 3-stage pipeline.
// C[b][m][n] = scale * sum_k (Ah+Al)[b][m][k] * (Bh+Bl)[b][n][k]  (+ bias)
// OUT: 0 -> f32 Cf   1 -> split bf16 (Ch, Cl)
// BM : 0 none, 1 row-bias bias[m], 2 col-bias bias[n]
// ---------------------------------------------------------------------------
template<int OUT, int BM>
__global__ __launch_bounds__(256) void k_gemm(
    const bf16* __restrict__ Ah, const bf16* __restrict__ Al,
    const bf16* __restrict__ Bh, const bf16* __restrict__ Bl,
    const float* __restrict__ bias,
    float* __restrict__ Cf, bf16* __restrict__ Ch, bf16* __restrict__ Cl,
    int M, int N, int K, size_t strA, size_t strB, size_t strC, float scale)
{
    __shared__ uint32_t sm[STAGES][4][128 * 8];  // 48KB

    const int tid = threadIdx.x, lane = tid & 31, wid = tid >> 5;
    const int wm = wid >> 2, wn = wid & 3, g = lane >> 2, q = lane & 3;
    const int m0 = blockIdx.y * 128, n0 = blockIdx.x * 128;
    const size_t zb = blockIdx.z;

    const int r = tid >> 1, h = tid & 1;
    const bf16* pAh = Ah + zb * strA + (size_t)(m0 + r) * K + 8 * h;
    const bf16* pAl = Al + zb * strA + (size_t)(m0 + r) * K + 8 * h;
    const bf16* pBh = Bh + zb * strB + (size_t)(n0 + r) * K + 8 * h;
    const bf16* pBl = Bl + zb * strB + (size_t)(n0 + r) * K + 8 * h;
    const uint32_t dOff = (uint32_t)((r * 8 + ((4 * h) ^ (r & 4))) * 4);

    const int nIt = K >> 4;

    auto issue = [&](int s) {
        if (s < nIt) {
            size_t ko = (size_t)s * 16;
            int sb = s % STAGES;
            uint32_t b0 = (uint32_t)__cvta_generic_to_shared(&sm[sb][0][0]) + dOff;
            uint32_t b1 = (uint32_t)__cvta_generic_to_shared(&sm[sb][1][0]) + dOff;
            uint32_t b2 = (uint32_t)__cvta_generic_to_shared(&sm[sb][2][0]) + dOff;
            uint32_t b3 = (uint32_t)__cvta_generic_to_shared(&sm[sb][3][0]) + dOff;
            cpasync16(b0, pAh + ko);
            cpasync16(b1, pAl + ko);
            cpasync16(b2, pBh + ko);
            cpasync16(b3, pBl + ko);
        }
        asm volatile("cp.async.commit_group;");
    };

    float acc[4][4][4] = {};

    issue(0);
    issue(1);

    for (int it = 0; it < nIt; it++) {
        asm volatile("cp.async.wait_group 1;");
        __syncthreads();
        issue(it + 2);

        const int cb = it % STAGES;
        const uint32_t* SAh = sm[cb][0];
        const uint32_t* SAl = sm[cb][1];
        const uint32_t* SBh = sm[cb][2];
        const uint32_t* SBl = sm[cb][3];

        uint32_t ah[4][4], al[4][4], bh[4][2], bl[4][2];
#pragma unroll
        for (int mt = 0; mt < 4; mt++) {
            ldmA(ah[mt], SAh, wm * 64 + mt * 16, lane);
            ldmA(al[mt], SAl, wm * 64 + mt * 16, lane);
        }
#pragma unroll
        for (int nt = 0; nt < 4; nt++) {
            ldmB(bh[nt], SBh, wn * 32 + nt * 8, lane);
            ldmB(bl[nt], SBl, wn * 32 + nt * 8, lane);
        }
#pragma unroll
        for (int mt = 0; mt < 4; mt++)
#pragma unroll
            for (int nt = 0; nt < 4; nt++) {
                mma(acc[mt][nt], ah[mt], bl[nt]);
                mma(acc[mt][nt], al[mt], bh[nt]);
                mma(acc[mt][nt], ah[mt], bh[nt]);
            }
    }

    // epilogue
    float* Cfb = (OUT == 0) ? Cf + zb * strC : nullptr;
    bf16* Chb = (OUT == 1) ? Ch + zb * strC : nullptr;
    bf16* Clb = (OUT == 1) ? Cl + zb * strC : nullptr;

#pragma unroll
    for (int mt = 0; mt < 4; mt++) {
        const int rr = m0 + wm * 64 + mt * 16 + g;
        float br0 = 0.f, br1 = 0.f;
        if (BM == 1) { br0 = bias[rr]; br1 = bias[rr + 8]; }
#pragma unroll
        for (int nt = 0; nt < 4; nt++) {
            const int cc = n0 + wn * 32 + nt * 8 + 2 * q;
            float v0 = acc[mt][nt][0] * scale, v1 = acc[mt][nt][1] * scale;
            float v2 = acc[mt][nt][2] * scale, v3 = acc[mt][nt][3] * scale;
            if (BM == 1) { v0 += br0; v1 += br0; v2 += br1; v3 += br1; }
            if (BM == 2) {
                float bc0 = bias[cc], bc1 = bias[cc + 1];
                v0 += bc0; v1 += bc1; v2 += bc0; v3 += bc1;
            }
            if (OUT == 0) {
                *reinterpret_cast<float2*>(&Cfb[(size_t)rr * N + cc]) = make_float2(v0, v1);
                *reinterpret_cast<float2*>(&Cfb[(size_t)(rr + 8) * N + cc]) = make_float2(v2, v3);
            } else {
                bf16 h0, l0, h1, l1, h2, l2, h3, l3;
                split1(v0, h0, l0); split1(v1, h1, l1);
                split1(v2, h2, l2); split1(v3, h3, l3);
                *reinterpret_cast<__nv_bfloat162*>(&Chb[(size_t)rr * N + cc]) =
                    __nv_bfloat162(h0, h1);
                *reinterpret_cast<__nv_bfloat162*>(&Clb[(size_t)rr * N + cc]) =
                    __nv_bfloat162(l0, l1);
                *reinterpret_cast<__nv_bfloat162*>(&Chb[(size_t)(rr + 8) * N + cc]) =
                    __nv_bfloat162(h2, h3);
                *reinterpret_cast<__nv_bfloat162*>(&Clb[(size_t)(rr + 8) * N + cc]) =
                    __nv_bfloat162(l2, l3);
            }
        }
    }
}

// ---------------------------------------------------------------------------
// transpose + split: [DIM][NTOK] f32 -> [NTOK][DIM] hi/lo bf16, batched
// ---------------------------------------------------------------------------
__global__ __launch_bounds__(256) void k_splitT(const float* __restrict__ in,
                                                bf16* __restrict__ oh,
                                                bf16* __restrict__ ol)
{
    __shared__ float t[32][33];
    const float* ib = in + (size_t)blockIdx.z * DIM * NTOK;
    bf16* ohb = oh + (size_t)blockIdx.z * NTOK * DIM;
    bf16* olb = ol + (size_t)blockIdx.z * NTOK * DIM;
    const int n0 = blockIdx.x * 32, c0 = blockIdx.y * 32;
    const int tx = threadIdx.x & 31, ty = threadIdx.x >> 5;
#pragma unroll
    for (int j = 0; j < 4; j++)
        t[ty + 8 * j][tx] = ib[(size_t)(c0 + ty + 8 * j) * NTOK + n0 + tx];
    __syncthreads();
#pragma unroll
    for (int j = 0; j < 4; j++) {
        float x = t[tx][ty + 8 * j];
        bf16 h, l;
        split1(x, h, l);
        size_t idx = (size_t)(n0 + ty + 8 * j) * DIM + c0 + tx;
        ohb[idx] = h;
        olb[idx] = l;
    }
}

// elementwise split for weights
__global__ __launch_bounds__(256) void k_splitW(const float* __restrict__ w,
                                                bf16* __restrict__ oh,
                                                bf16* __restrict__ ol)
{
    int i = blockIdx.x * 256 + threadIdx.x;
    float4 v = reinterpret_cast<const float4*>(w)[i];
    bf16 h0, l0, h1, l1, h2, l2, h3, l3;
    split1(v.x, h0, l0); split1(v.y, h1, l1);
    split1(v.z, h2, l2); split1(v.w, h3, l3);
    reinterpret_cast<__nv_bfloat162*>(oh)[2 * i]     = __nv_bfloat162(h0, h1);
    reinterpret_cast<__nv_bfloat162*>(oh)[2 * i + 1] = __nv_bfloat162(h2, h3);
    reinterpret_cast<__nv_bfloat162*>(ol)[2 * i]     = __nv_bfloat162(l0, l1);
    reinterpret_cast<__nv_bfloat162*>(ol)[2 * i + 1] = __nv_bfloat162(l2, l3);
}

// ---------------------------------------------------------------------------
// Row softmax: f32 in, split bf16 out. One CTA per row of 1024.
// ---------------------------------------------------------------------------
__global__ __launch_bounds__(256) void k_softmax(const float* __restrict__ S,
                                                 bf16* __restrict__ Ph,
                                                 bf16* __restrict__ Pl)
{
    const float* row = S + (size_t)blockIdx.x * NTOK;
    const int tid = threadIdx.x;
    __shared__ float red[8];

    float4 v = reinterpret_cast<const float4*>(row)[tid];
    float m = fmaxf(fmaxf(v.x, v.y), fmaxf(v.z, v.w));
#pragma unroll
    for (int o = 16; o > 0; o >>= 1)
        m = fmaxf(m, __shfl_xor_sync(0xffffffffu, m, o));
    if ((tid & 31) == 0) red[tid >> 5] = m;
    __syncthreads();
    float mall = fmaxf(fmaxf(red[0], red[1]), fmaxf(red[2], red[3]));
    mall = fmaxf(mall, fmaxf(fmaxf(red[4], red[5]), fmaxf(red[6], red[7])));

    float4 e;
    e.x = expf(v.x - mall);
    e.y = expf(v.y - mall);
    e.z = expf(v.z - mall);
    e.w = expf(v.w - mall);
    float s = e.x + e.y + e.z + e.w;
#pragma unroll
    for (int o = 16; o > 0; o >>= 1)
        s += __shfl_xor_sync(0xffffffffu, s, o);
    __syncthreads();
    if ((tid & 31) == 0) red[tid >> 5] = s;
    __syncthreads();
    float sall = red[0] + red[1] + red[2] + red[3] + red[4] + red[5] + red[6] + red[7];
    float inv = 1.0f / sall;
    e.x *= inv; e.y *= inv; e.z *= inv; e.w *= inv;

    bf16 h0, l0, h1, l1, h2, l2, h3, l3;
    split1(e.x, h0, l0); split1(e.y, h1, l1);
    split1(e.z, h2, l2); split1(e.w, h3, l3);
    bf16* ph = Ph + (size_t)blockIdx.x * NTOK + 4 * tid;
    bf16* pl = Pl + (size_t)blockIdx.x * NTOK + 4 * tid;
    reinterpret_cast<__nv_bfloat162*>(ph)[0] = __nv_bfloat162(h0, h1);
    reinterpret_cast<__nv_bfloat162*>(ph)[1] = __nv_bfloat162(h2, h3);
    reinterpret_cast<__nv_bfloat162*>(pl)[0] = __nv_bfloat162(l0, l1);
    reinterpret_cast<__nv_bfloat162*>(pl)[1] = __nv_bfloat162(l2, l3);
}

// ---------------------------------------------------------------------------
extern "C" void kernel_launch(void* const* d_in, const int* in_sizes, int n_in,
                              void* d_out, int out_size)
{
    const float* rgb = (const float*)d_in[0];
    const float* ms  = (const float*)d_in[1];
    const float* Wq  = (const float*)d_in[2];
    const float* bq  = (const float*)d_in[3];
    const float* Wk  = (const float*)d_in[4];
    const float* bk  = (const float*)d_in[5];
    const float* Wv  = (const float*)d_in[6];
    const float* bv  = (const float*)d_in[7];
    const float* Wf  = (const float*)d_in[8];
    const float* bf_ = (const float*)d_in[9];
    float* out = (float*)d_out;

    bf16 *t1h, *t1l, *t2h, *t2l, *qh, *ql, *kh, *kl, *vh, *vl, *oh, *ol, *Ph, *Pl, *wh, *wl;
    float* s;
    cudaGetSymbolAddress((void**)&t1h, g_t1h); cudaGetSymbolAddress((void**)&t1l, g_t1l);
    cudaGetSymbolAddress((void**)&t2h, g_t2h); cudaGetSymbolAddress((void**)&t2l, g_t2l);
    cudaGetSymbolAddress((void**)&qh,  g_qh);  cudaGetSymbolAddress((void**)&ql,  g_ql);
    cudaGetSymbolAddress((void**)&kh,  g_kh);  cudaGetSymbolAddress((void**)&kl,  g_kl);
    cudaGetSymbolAddress((void**)&vh,  g_vh);  cudaGetSymbolAddress((void**)&vl,  g_vl);
    cudaGetSymbolAddress((void**)&oh,  g_oh);  cudaGetSymbolAddress((void**)&ol,  g_ol);
    cudaGetSymbolAddress((void**)&Ph,  g_Ph);  cudaGetSymbolAddress((void**)&Pl,  g_Pl);
    cudaGetSymbolAddress((void**)&wh,  g_wh);  cudaGetSymbolAddress((void**)&wl,  g_wl);
    cudaGetSymbolAddress((void**)&s,   g_s);

    bf16 *wqh = wh,          *wql = wl;
    bf16 *wkh = wh + WW,     *wkl = wl + WW;
    bf16 *wvh = wh + 2 * WW, *wvl = wl + 2 * WW;
    bf16 *wfh = wh + 3 * WW, *wfl = wl + 3 * WW;

    const float scale = 1.0f / sqrtf((float)DIM);
    const size_t nd = (size_t)NTOK * DIM;
    const size_t nn = (size_t)NTOK * NTOK;

    dim3 blk(256);
    dim3 gT(NTOK / 32, DIM / 32, BATCH);
    const int wBlocks = (int)(WW / (256 * 4));  // 144

    k_splitT<<<gT, blk>>>(rgb, t1h, t1l);
    k_splitT<<<gT, blk>>>(ms,  t2h, t2l);
    k_splitW<<<wBlocks, blk>>>(Wq, wqh, wql);
    k_splitW<<<wBlocks, blk>>>(Wk, wkh, wkl);
    k_splitW<<<wBlocks, blk>>>(Wv, wvh, wvl);
    k_splitW<<<wBlocks, blk>>>(Wf, wfh, wfl);

    dim3 gQ(DIM / 128, NTOK / 128, BATCH);   // (3, 8, 32)
    dim3 gV(NTOK / 128, DIM / 128, BATCH);   // (8, 3, 32)
    dim3 gS(NTOK / 128, NTOK / 128, BATCH);  // (8, 8, 32)

    // qT[n][d] = t1[n][c] . Wq[d][c] + bq[d]  (col bias, split out)
    k_gemm<1, 2><<<gQ, blk>>>(t1h, t1l, wqh, wql, bq, nullptr, qh, ql,
                              NTOK, DIM, DIM, nd, 0, nd, 1.0f);
    k_gemm<1, 2><<<gQ, blk>>>(t2h, t2l, wkh, wkl, bk, nullptr, kh, kl,
                              NTOK, DIM, DIM, nd, 0, nd, 1.0f);
    // v[d][n] = Wv[d][c] . t2[n][c] + bv[d]  (row bias, split out)
    k_gemm<1, 1><<<gV, blk>>>(wvh, wvl, t2h, t2l, bv, nullptr, vh, vl,
                              DIM, NTOK, DIM, 0, nd, nd, 1.0f);
    // S[i][j] = scale * qT[i][:] . kT[j][:]  (f32 out)
    k_gemm<0, 0><<<gS, blk>>>(qh, ql, kh, kl, nullptr, s, nullptr, nullptr,
                              NTOK, NTOK, DIM, nd, nd, nn, scale);

    k_softmax<<<BATCH * NTOK, 256>>>(s, Ph, Pl);

    // oT[n][d] = P[n][m] . v[d][m]  (split out)
    k_gemm<1, 0><<<gQ, blk>>>(Ph, Pl, vh, vl, nullptr, nullptr, oh, ol,
                              NTOK, DIM, NTOK, nn, nd, nd, 1.0f);
    // out[d][n] = Wf[d][c] . oT[n][c] + bf[d]  (f32 out, row bias)
    k_gemm<0, 1><<<gV, blk>>>(wfh, wfl, oh, ol, bf_, out, nullptr, nullptr,
                              DIM, NTOK, DIM, 0, nd, nd, 1.0f);
}

// round 8
// speedup vs baseline: 2.5117x; 1.1792x over previous
#include <cuda_runtime.h>
#include <cuda_bf16.h>
#include <math.h>
#include <stdint.h>

#define BATCH 32
#define DIM   384
#define NTOK  1024
#define STAGES 3

typedef __nv_bfloat16 bf16;

// ---------------------------------------------------------------------------
// Scratch (allocation-free rule: __device__ globals). All operands pre-split
// into hi/lo bf16 pairs; S kept in f32 for softmax precision.
// ---------------------------------------------------------------------------
#define ND ((size_t)BATCH * NTOK * DIM)
#define NN ((size_t)BATCH * NTOK * NTOK)
#define WW ((size_t)DIM * DIM)

__device__ bf16 g_t1h[ND], g_t1l[ND];   // rgb^T [n][c]
__device__ bf16 g_t2h[ND], g_t2l[ND];   // ms^T  [n][c]
__device__ bf16 g_qh[ND],  g_ql[ND];    // qT [n][d]
__device__ bf16 g_kh[ND],  g_kl[ND];    // kT [n][d]
__device__ bf16 g_vh[ND],  g_vl[ND];    // v  [d][n]
__device__ bf16 g_oh[ND],  g_ol[ND];    // oT [n][d]
__device__ bf16 g_Ph[NN],  g_Pl[NN];    // attn [i][m]
__device__ float g_s[NN];               // scores f32
__device__ bf16 g_wh[4 * WW], g_wl[4 * WW]; // Wq,Wk,Wv,Wf split

// ---------------------------------------------------------------------------
// helpers
// ---------------------------------------------------------------------------
__device__ __forceinline__ void split1(float x, bf16& h, bf16& l) {
    h = __float2bfloat16(x);
    l = __float2bfloat16(x - __bfloat162float(h));
}

__device__ __forceinline__ void cpasync16(uint32_t dst, const void* src) {
    asm volatile("cp.async.cg.shared.global [%0], [%1], 16;" :: "r"(dst), "l"(src));
}

__device__ __forceinline__ void ldmA(uint32_t f[4], const uint32_t* base, int rb, int lane) {
    int t = lane >> 3, rr = lane & 7;
    int row = rb + rr + (t & 1) * 8;
    int c = ((t >> 1) << 2) ^ (row & 4);
    uint32_t sa = (uint32_t)__cvta_generic_to_shared(&base[row * 8 + c]);
    asm volatile("ldmatrix.sync.aligned.m8n8.x4.shared.b16 {%0,%1,%2,%3}, [%4];"
                 : "=r"(f[0]), "=r"(f[1]), "=r"(f[2]), "=r"(f[3]) : "r"(sa));
}

__device__ __forceinline__ void ldmB(uint32_t f[2], const uint32_t* base, int cb, int lane) {
    int row = cb + (lane & 7);
    int c = (((lane >> 3) & 1) << 2) ^ (row & 4);
    uint32_t sa = (uint32_t)__cvta_generic_to_shared(&base[row * 8 + c]);
    asm volatile("ldmatrix.sync.aligned.m8n8.x2.shared.b16 {%0,%1}, [%2];"
                 : "=r"(f[0]), "=r"(f[1]) : "r"(sa));
}

__device__ __forceinline__ void mma(float acc[4], const uint32_t a[4], const uint32_t b[2]) {
    asm volatile("mma.sync.aligned.m16n8k16.row.col.f32.bf16.bf16.f32 "
                 "{%0,%1,%2,%3}, {%4,%5,%6,%7}, {%8,%9}, {%0,%1,%2,%3};"
                 : "+f"(acc[0]), "+f"(acc[1]), "+f"(acc[2]), "+f"(acc[3])
                 : "r"(a[0]), "r"(a[1]), "r"(a[2]), "r"(a[3]), "r"(b[0]), "r"(b[1]));
}

// ---------------------------------------------------------------------------
// Universal NT GEMM over pre-split bf16 operands, cp.async 3-stage pipeline.
// C[b][m][n] = scale * sum_k (Ah+Al)[b][m][k] * (Bh+Bl)[b][n][k]  (+ bias)
// OUT: 0 -> f32 Cf   1 -> split bf16 (Ch, Cl)
// BM : 0 none, 1 row-bias bias[m], 2 col-bias bias[n]
// CTA 128x128, 256 threads, 2 CTAs/SM.
// ---------------------------------------------------------------------------
template<int OUT, int BM>
__global__ __launch_bounds__(256, 2) void k_gemm(
    const bf16* __restrict__ Ah, const bf16* __restrict__ Al,
    const bf16* __restrict__ Bh, const bf16* __restrict__ Bl,
    const float* __restrict__ bias,
    float* __restrict__ Cf, bf16* __restrict__ Ch, bf16* __restrict__ Cl,
    int M, int N, int K, size_t strA, size_t strB, size_t strC, float scale)
{
    __shared__ uint32_t sm[STAGES][4][128 * 8];  // 48KB

    const int tid = threadIdx.x, lane = tid & 31, wid = tid >> 5;
    const int wm = wid >> 2, wn = wid & 3, g = lane >> 2, q = lane & 3;
    const int m0 = blockIdx.y * 128, n0 = blockIdx.x * 128;
    const size_t zb = blockIdx.z;

    const int r = tid >> 1, h = tid & 1;
    const bf16* pAh = Ah + zb * strA + (size_t)(m0 + r) * K + 8 * h;
    const bf16* pAl = Al + zb * strA + (size_t)(m0 + r) * K + 8 * h;
    const bf16* pBh = Bh + zb * strB + (size_t)(n0 + r) * K + 8 * h;
    const bf16* pBl = Bl + zb * strB + (size_t)(n0 + r) * K + 8 * h;
    const uint32_t dOff = (uint32_t)((r * 8 + ((4 * h) ^ (r & 4))) * 4);

    const int nIt = K >> 4;

    auto issue = [&](int s) {
        if (s < nIt) {
            size_t ko = (size_t)s * 16;
            int sb = s % STAGES;
            uint32_t b0 = (uint32_t)__cvta_generic_to_shared(&sm[sb][0][0]) + dOff;
            uint32_t b1 = (uint32_t)__cvta_generic_to_shared(&sm[sb][1][0]) + dOff;
            uint32_t b2 = (uint32_t)__cvta_generic_to_shared(&sm[sb][2][0]) + dOff;
            uint32_t b3 = (uint32_t)__cvta_generic_to_shared(&sm[sb][3][0]) + dOff;
            cpasync16(b0, pAh + ko);
            cpasync16(b1, pAl + ko);
            cpasync16(b2, pBh + ko);
            cpasync16(b3, pBl + ko);
        }
        asm volatile("cp.async.commit_group;");
    };

    float acc[4][4][4] = {};

    issue(0);
    issue(1);

    for (int it = 0; it < nIt; it++) {
        asm volatile("cp.async.wait_group 1;");
        __syncthreads();
        issue(it + 2);

        const int cb = it % STAGES;
        const uint32_t* SAh = sm[cb][0];
        const uint32_t* SAl = sm[cb][1];
        const uint32_t* SBh = sm[cb][2];
        const uint32_t* SBl = sm[cb][3];

        // B fragments for all 4 n-tiles (16 regs)
        uint32_t bh[4][2], bl[4][2];
#pragma unroll
        for (int nt = 0; nt < 4; nt++) {
            ldmB(bh[nt], SBh, wn * 32 + nt * 8, lane);
            ldmB(bl[nt], SBl, wn * 32 + nt * 8, lane);
        }

        // Two m-halves; within each, term-major ordering so consecutive MMAs
        // hit independent accumulators (8-deep independence per term).
#pragma unroll
        for (int mh = 0; mh < 2; mh++) {
            uint32_t ah[2][4], al[2][4];
#pragma unroll
            for (int m2 = 0; m2 < 2; m2++) {
                ldmA(ah[m2], SAh, wm * 64 + (mh * 2 + m2) * 16, lane);
                ldmA(al[m2], SAl, wm * 64 + (mh * 2 + m2) * 16, lane);
            }
            // term 1: Ah x Bl
#pragma unroll
            for (int m2 = 0; m2 < 2; m2++)
#pragma unroll
                for (int nt = 0; nt < 4; nt++)
                    mma(acc[mh * 2 + m2][nt], ah[m2], bl[nt]);
            // term 2: Al x Bh
#pragma unroll
            for (int m2 = 0; m2 < 2; m2++)
#pragma unroll
                for (int nt = 0; nt < 4; nt++)
                    mma(acc[mh * 2 + m2][nt], al[m2], bh[nt]);
            // term 3: Ah x Bh
#pragma unroll
            for (int m2 = 0; m2 < 2; m2++)
#pragma unroll
                for (int nt = 0; nt < 4; nt++)
                    mma(acc[mh * 2 + m2][nt], ah[m2], bh[nt]);
        }
    }

    // epilogue
    float* Cfb = (OUT == 0) ? Cf + zb * strC : nullptr;
    bf16* Chb = (OUT == 1) ? Ch + zb * strC : nullptr;
    bf16* Clb = (OUT == 1) ? Cl + zb * strC : nullptr;

#pragma unroll
    for (int mt = 0; mt < 4; mt++) {
        const int rr = m0 + wm * 64 + mt * 16 + g;
        float br0 = 0.f, br1 = 0.f;
        if (BM == 1) { br0 = bias[rr]; br1 = bias[rr + 8]; }
#pragma unroll
        for (int nt = 0; nt < 4; nt++) {
            const int cc = n0 + wn * 32 + nt * 8 + 2 * q;
            float v0 = acc[mt][nt][0] * scale, v1 = acc[mt][nt][1] * scale;
            float v2 = acc[mt][nt][2] * scale, v3 = acc[mt][nt][3] * scale;
            if (BM == 1) { v0 += br0; v1 += br0; v2 += br1; v3 += br1; }
            if (BM == 2) {
                float bc0 = bias[cc], bc1 = bias[cc + 1];
                v0 += bc0; v1 += bc1; v2 += bc0; v3 += bc1;
            }
            if (OUT == 0) {
                *reinterpret_cast<float2*>(&Cfb[(size_t)rr * N + cc]) = make_float2(v0, v1);
                *reinterpret_cast<float2*>(&Cfb[(size_t)(rr + 8) * N + cc]) = make_float2(v2, v3);
            } else {
                bf16 h0, l0, h1, l1, h2, l2, h3, l3;
                split1(v0, h0, l0); split1(v1, h1, l1);
                split1(v2, h2, l2); split1(v3, h3, l3);
                *reinterpret_cast<__nv_bfloat162*>(&Chb[(size_t)rr * N + cc]) =
                    __nv_bfloat162(h0, h1);
                *reinterpret_cast<__nv_bfloat162*>(&Clb[(size_t)rr * N + cc]) =
                    __nv_bfloat162(l0, l1);
                *reinterpret_cast<__nv_bfloat162*>(&Chb[(size_t)(rr + 8) * N + cc]) =
                    __nv_bfloat162(h2, h3);
                *reinterpret_cast<__nv_bfloat162*>(&Clb[(size_t)(rr + 8) * N + cc]) =
                    __nv_bfloat162(l2, l3);
            }
        }
    }
}

// ---------------------------------------------------------------------------
// transpose + split: [DIM][NTOK] f32 -> [NTOK][DIM] hi/lo bf16, batched
// ---------------------------------------------------------------------------
__global__ __launch_bounds__(256) void k_splitT(const float* __restrict__ in,
                                                bf16* __restrict__ oh,
                                                bf16* __restrict__ ol)
{
    __shared__ float t[32][33];
    const float* ib = in + (size_t)blockIdx.z * DIM * NTOK;
    bf16* ohb = oh + (size_t)blockIdx.z * NTOK * DIM;
    bf16* olb = ol + (size_t)blockIdx.z * NTOK * DIM;
    const int n0 = blockIdx.x * 32, c0 = blockIdx.y * 32;
    const int tx = threadIdx.x & 31, ty = threadIdx.x >> 5;
#pragma unroll
    for (int j = 0; j < 4; j++)
        t[ty + 8 * j][tx] = ib[(size_t)(c0 + ty + 8 * j) * NTOK + n0 + tx];
    __syncthreads();
#pragma unroll
    for (int j = 0; j < 4; j++) {
        float x = t[tx][ty + 8 * j];
        bf16 h, l;
        split1(x, h, l);
        size_t idx = (size_t)(n0 + ty + 8 * j) * DIM + c0 + tx;
        ohb[idx] = h;
        olb[idx] = l;
    }
}

// elementwise split for weights
__global__ __launch_bounds__(256) void k_splitW(const float* __restrict__ w,
                                                bf16* __restrict__ oh,
                                                bf16* __restrict__ ol)
{
    int i = blockIdx.x * 256 + threadIdx.x;
    float4 v = reinterpret_cast<const float4*>(w)[i];
    bf16 h0, l0, h1, l1, h2, l2, h3, l3;
    split1(v.x, h0, l0); split1(v.y, h1, l1);
    split1(v.z, h2, l2); split1(v.w, h3, l3);
    reinterpret_cast<__nv_bfloat162*>(oh)[2 * i]     = __nv_bfloat162(h0, h1);
    reinterpret_cast<__nv_bfloat162*>(oh)[2 * i + 1] = __nv_bfloat162(h2, h3);
    reinterpret_cast<__nv_bfloat162*>(ol)[2 * i]     = __nv_bfloat162(l0, l1);
    reinterpret_cast<__nv_bfloat162*>(ol)[2 * i + 1] = __nv_bfloat162(l2, l3);
}

// ---------------------------------------------------------------------------
// Row softmax: f32 in, split bf16 out. One CTA per row of 1024.
// ---------------------------------------------------------------------------
__global__ __launch_bounds__(256) void k_softmax(const float* __restrict__ S,
                                                 bf16* __restrict__ Ph,
                                                 bf16* __restrict__ Pl)
{
    const float* row = S + (size_t)blockIdx.x * NTOK;
    const int tid = threadIdx.x;
    __shared__ float red[8];

    float4 v = reinterpret_cast<const float4*>(row)[tid];
    float m = fmaxf(fmaxf(v.x, v.y), fmaxf(v.z, v.w));
#pragma unroll
    for (int o = 16; o > 0; o >>= 1)
        m = fmaxf(m, __shfl_xor_sync(0xffffffffu, m, o));
    if ((tid & 31) == 0) red[tid >> 5] = m;
    __syncthreads();
    float mall = fmaxf(fmaxf(red[0], red[1]), fmaxf(red[2], red[3]));
    mall = fmaxf(mall, fmaxf(fmaxf(red[4], red[5]), fmaxf(red[6], red[7])));

    float4 e;
    e.x = expf(v.x - mall);
    e.y = expf(v.y - mall);
    e.z = expf(v.z - mall);
    e.w = expf(v.w - mall);
    float s = e.x + e.y + e.z + e.w;
#pragma unroll
    for (int o = 16; o > 0; o >>= 1)
        s += __shfl_xor_sync(0xffffffffu, s, o);
    __syncthreads();
    if ((tid & 31) == 0) red[tid >> 5] = s;
    __syncthreads();
    float sall = red[0] + red[1] + red[2] + red[3] + red[4] + red[5] + red[6] + red[7];
    float inv = 1.0f / sall;
    e.x *= inv; e.y *= inv; e.z *= inv; e.w *= inv;

    bf16 h0, l0, h1, l1, h2, l2, h3, l3;
    split1(e.x, h0, l0); split1(e.y, h1, l1);
    split1(e.z, h2, l2); split1(e.w, h3, l3);
    bf16* ph = Ph + (size_t)blockIdx.x * NTOK + 4 * tid;
    bf16* pl = Pl + (size_t)blockIdx.x * NTOK + 4 * tid;
    reinterpret_cast<__nv_bfloat162*>(ph)[0] = __nv_bfloat162(h0, h1);
    reinterpret_cast<__nv_bfloat162*>(ph)[1] = __nv_bfloat162(h2, h3);
    reinterpret_cast<__nv_bfloat162*>(pl)[0] = __nv_bfloat162(l0, l1);
    reinterpret_cast<__nv_bfloat162*>(pl)[1] = __nv_bfloat162(l2, l3);
}

// ---------------------------------------------------------------------------
extern "C" void kernel_launch(void* const* d_in, const int* in_sizes, int n_in,
                              void* d_out, int out_size)
{
    const float* rgb = (const float*)d_in[0];
    const float* ms  = (const float*)d_in[1];
    const float* Wq  = (const float*)d_in[2];
    const float* bq  = (const float*)d_in[3];
    const float* Wk  = (const float*)d_in[4];
    const float* bk  = (const float*)d_in[5];
    const float* Wv  = (const float*)d_in[6];
    const float* bv  = (const float*)d_in[7];
    const float* Wf  = (const float*)d_in[8];
    const float* bf_ = (const float*)d_in[9];
    float* out = (float*)d_out;

    bf16 *t1h, *t1l, *t2h, *t2l, *qh, *ql, *kh, *kl, *vh, *vl, *oh, *ol, *Ph, *Pl, *wh, *wl;
    float* s;
    cudaGetSymbolAddress((void**)&t1h, g_t1h); cudaGetSymbolAddress((void**)&t1l, g_t1l);
    cudaGetSymbolAddress((void**)&t2h, g_t2h); cudaGetSymbolAddress((void**)&t2l, g_t2l);
    cudaGetSymbolAddress((void**)&qh,  g_qh);  cudaGetSymbolAddress((void**)&ql,  g_ql);
    cudaGetSymbolAddress((void**)&kh,  g_kh);  cudaGetSymbolAddress((void**)&kl,  g_kl);
    cudaGetSymbolAddress((void**)&vh,  g_vh);  cudaGetSymbolAddress((void**)&vl,  g_vl);
    cudaGetSymbolAddress((void**)&oh,  g_oh);  cudaGetSymbolAddress((void**)&ol,  g_ol);
    cudaGetSymbolAddress((void**)&Ph,  g_Ph);  cudaGetSymbolAddress((void**)&Pl,  g_Pl);
    cudaGetSymbolAddress((void**)&wh,  g_wh);  cudaGetSymbolAddress((void**)&wl,  g_wl);
    cudaGetSymbolAddress((void**)&s,   g_s);

    bf16 *wqh = wh,          *wql = wl;
    bf16 *wkh = wh + WW,     *wkl = wl + WW;
    bf16 *wvh = wh + 2 * WW, *wvl = wl + 2 * WW;
    bf16 *wfh = wh + 3 * WW, *wfl = wl + 3 * WW;

    const float scale = 1.0f / sqrtf((float)DIM);
    const size_t nd = (size_t)NTOK * DIM;
    const size_t nn = (size_t)NTOK * NTOK;

    dim3 blk(256);
    dim3 gT(NTOK / 32, DIM / 32, BATCH);
    const int wBlocks = (int)(WW / (256 * 4));  // 144

    k_splitT<<<gT, blk>>>(rgb, t1h, t1l);
    k_splitT<<<gT, blk>>>(ms,  t2h, t2l);
    k_splitW<<<wBlocks, blk>>>(Wq, wqh, wql);
    k_splitW<<<wBlocks, blk>>>(Wk, wkh, wkl);
    k_splitW<<<wBlocks, blk>>>(Wv, wvh, wvl);
    k_splitW<<<wBlocks, blk>>>(Wf, wfh, wfl);

    dim3 gQ(DIM / 128, NTOK / 128, BATCH);   // (3, 8, 32)
    dim3 gV(NTOK / 128, DIM / 128, BATCH);   // (8, 3, 32)
    dim3 gS(NTOK / 128, NTOK / 128, BATCH);  // (8, 8, 32)

    // qT[n][d] = t1[n][c] . Wq[d][c] + bq[d]  (col bias, split out)
    k_gemm<1, 2><<<gQ, blk>>>(t1h, t1l, wqh, wql, bq, nullptr, qh, ql,
                              NTOK, DIM, DIM, nd, 0, nd, 1.0f);
    k_gemm<1, 2><<<gQ, blk>>>(t2h, t2l, wkh, wkl, bk, nullptr, kh, kl,
                              NTOK, DIM, DIM, nd, 0, nd, 1.0f);
    // v[d][n] = Wv[d][c] . t2[n][c] + bv[d]  (row bias, split out)
    k_gemm<1, 1><<<gV, blk>>>(wvh, wvl, t2h, t2l, bv, nullptr, vh, vl,
                              DIM, NTOK, DIM, 0, nd, nd, 1.0f);
    // S[i][j] = scale * qT[i][:] . kT[j][:]  (f32 out)
    k_gemm<0, 0><<<gS, blk>>>(qh, ql, kh, kl, nullptr, s, nullptr, nullptr,
                              NTOK, NTOK, DIM, nd, nd, nn, scale);

    k_softmax<<<BATCH * NTOK, 256>>>(s, Ph, Pl);

    // oT[n][d] = P[n][m] . v[d][m]  (split out)
    k_gemm<1, 0><<<gQ, blk>>>(Ph, Pl, vh, vl, nullptr, nullptr, oh, ol,
                              NTOK, DIM, NTOK, nn, nd, nd, 1.0f);
    // out[d][n] = Wf[d][c] . oT[n][c] + bf[d]  (f32 out, row bias)
    k_gemm<0, 1><<<gV, blk>>>(wfh, wfl, oh, ol, bf_, out, nullptr, nullptr,
                              DIM, NTOK, DIM, 0, nd, nd, 1.0f);
}